// round 16
// baseline (speedup 1.0000x reference)
#include <cuda_runtime.h>
#include <cuda_fp16.h>
#include <cstdint>

// ============================================================================
// LSTMCell on sm_100 (baseline PTX). mma.sync.m16n8k16 f16/f32.
// R13 -> R14/R15/R16: attack makespan quantization + SMSP latency hiding.
//   1024 CTAs / 296 slots = makespan 4 vs avg 3.46 -> 13.6% tail idle
//   (config-invariant residual seen in R7..R13). BN 128 -> 64: 2048 CTAs,
//   3 CTAs/SM (smem 72KB, regs<=84): makespan eff 86.4% -> 92.2%, and
//   6 warps/SMSP (vs 4) for latency hiding. No repack needed: a 64-col B
//   slice is a contiguous 8KB half of the 16KB block (swizzle is row-local).
// (R15/R16 = identical resubmits: infra failed before compile/run.)
// ============================================================================

#define BATCH 4096
#define KTOT  2048
#define NT_K 32                    // 2048/64 k-chunks
#define TILE_BYTES 16384           // 128 x 64 halfs, swizzled block
#define A_STAGE 16384              // A: 128 rows x 64 halfs
#define B_STAGE 8192               // B: 64 rows x 64 halfs (half block)
#define STAGE_BYTES 24576
#define NSTAGE 3
#define SMEM_MAIN  (NSTAGE * STAGE_BYTES)   // 73728
#define SMEM_TOTAL (SMEM_MAIN + 128)

__device__ __align__(1024) unsigned char g_Apack[(size_t)32 * NT_K * TILE_BYTES];  // 16 MB
__device__ __align__(1024) unsigned char g_Bpack[(size_t)32 * NT_K * TILE_BYTES];  // 16 MB

// ---------------------------------------------------------------- helpers
__device__ __forceinline__ uint32_t smem_u32(const void* p) {
    uint32_t a;
    asm("{ .reg .u64 t; cvta.to.shared.u64 t, %1; cvt.u32.u64 %0, t; }" : "=r"(a) : "l"(p));
    return a;
}
#define MBARRIER_INIT(addr, cnt) \
    asm volatile("mbarrier.init.shared.b64 [%0], %1;" :: "r"((uint32_t)(addr)), "r"((uint32_t)(cnt)) : "memory")
#define MBARRIER_EXPECT_TX(addr, bytes) \
    asm volatile("mbarrier.arrive.expect_tx.shared.b64 _, [%0], %1;" :: "r"((uint32_t)(addr)), "r"((uint32_t)(bytes)) : "memory")
#define MBARRIER_ARRIVE(addr) \
    asm volatile("mbarrier.arrive.shared.b64 _, [%0];" :: "r"((uint32_t)(addr)) : "memory")

__device__ __forceinline__ void mbar_wait(uint32_t mbar, uint32_t phase) {
    asm volatile(
        "{\n\t"
        ".reg .pred P;\n\t"
        "LAB_WAIT%=:\n\t"
        "mbarrier.try_wait.parity.acquire.cta.shared::cta.b64 P, [%0], %1, 0x989680;\n\t"
        "@!P bra LAB_WAIT%=;\n\t"
        "}"
        :: "r"(mbar), "r"(phase) : "memory");
}
__device__ __forceinline__ void bulk_g2s(uint32_t dst, const void* src, uint32_t bytes, uint32_t mbar) {
    asm volatile(
        "cp.async.bulk.shared::cluster.global.mbarrier::complete_tx::bytes [%0], [%1], %2, [%3];"
        :: "r"(dst), "l"(src), "r"(bytes), "r"(mbar) : "memory");
}

// block-internal swizzle: rows of 128B (64 halfs), 16B chunk c16 XOR row.
__device__ __forceinline__ uint32_t swz(uint32_t r, uint32_t c16) {
    return r * 128u + (((c16 ^ (r & 7u)) & 7u) << 4);
}

__device__ __forceinline__ void ldsm_x4(uint32_t* r, uint32_t addr) {
    asm volatile("ldmatrix.sync.aligned.m8n8.x4.shared.b16 {%0,%1,%2,%3}, [%4];"
                 : "=r"(r[0]), "=r"(r[1]), "=r"(r[2]), "=r"(r[3]) : "r"(addr));
}
__device__ __forceinline__ void mma16816(float* c, const uint32_t* a, uint32_t b0, uint32_t b1) {
    asm volatile(
        "mma.sync.aligned.m16n8k16.row.col.f32.f16.f16.f32 "
        "{%0,%1,%2,%3}, {%4,%5,%6,%7}, {%8,%9}, {%0,%1,%2,%3};"
        : "+f"(c[0]), "+f"(c[1]), "+f"(c[2]), "+f"(c[3])
        : "r"(a[0]), "r"(a[1]), "r"(a[2]), "r"(a[3]), "r"(b0), "r"(b1));
}

__device__ __forceinline__ float sigm_f(float x) { return __fdividef(1.0f, 1.0f + __expf(-x)); }
__device__ __forceinline__ float tanh_f(float x) { return __fdividef(2.0f, 1.0f + __expf(-2.0f * x)) - 1.0f; }

// ---------------------------------------------------------------- merged pack (unchanged)
__global__ void __launch_bounds__(256) pack_all(const float* __restrict__ x,
                                                const float* __restrict__ h,
                                                const float* __restrict__ W,
                                                const float* __restrict__ V) {
    if (blockIdx.x < 1024) {
        const int kc = (int)blockIdx.x & 31;
        unsigned char* dst = g_Apack + ((size_t)blockIdx.x << 14);
        const int m0 = ((int)blockIdx.x >> 5) * 128, k0 = kc * 64;
        const float* srcb = (k0 < 1024) ? (x + (size_t)m0 * 1024 + k0)
                                        : (h + (size_t)m0 * 1024 + (k0 - 1024));
#pragma unroll
        for (int i = 0; i < 4; i++) {
            int idx = (int)threadIdx.x + i * 256;    // 0..1023 16B chunks
            uint32_t r = (uint32_t)(idx >> 3);
            uint32_t c16 = (uint32_t)(idx & 7);
            const float* s = srcb + (size_t)r * 1024 + c16 * 8;
            float4 v0 = *reinterpret_cast<const float4*>(s);
            float4 v1 = *reinterpret_cast<const float4*>(s + 4);
            __half2 h0 = __floats2half2_rn(v0.x, v0.y);
            __half2 h1 = __floats2half2_rn(v0.z, v0.w);
            __half2 h2 = __floats2half2_rn(v1.x, v1.y);
            __half2 h3 = __floats2half2_rn(v1.z, v1.w);
            uint4 pk = make_uint4(*reinterpret_cast<uint32_t*>(&h0), *reinterpret_cast<uint32_t*>(&h1),
                                  *reinterpret_cast<uint32_t*>(&h2), *reinterpret_cast<uint32_t*>(&h3));
            *reinterpret_cast<uint4*>(dst + swz(r, c16)) = pk;
        }
    } else {
        __shared__ float buf[32][33];
        const int idx0 = (int)blockIdx.x - 1024;
        const int nblk = idx0 & 127;   // orig n / 32
        const int kblk = idx0 >> 7;    // k / 32
        const int n0 = nblk * 32, k0 = kblk * 32;
        const float* src = (k0 < 1024) ? (W + (size_t)k0 * 4096 + n0)
                                       : (V + (size_t)(k0 - 1024) * 4096 + n0);
        for (int idx = threadIdx.x; idx < 1024; idx += 256) {
            int kl = idx >> 5, nl = idx & 31;
            buf[kl][nl] = src[(size_t)kl * 4096 + nl];
        }
        __syncthreads();
        const int kchunk = kblk >> 1;
        const int kbase = (kblk & 1) * 32;
        for (int idx = threadIdx.x; idx < 512; idx += 256) {
            int nl = idx >> 4;
            int kp = (idx & 15) * 2;
            int norig = n0 + nl;
            int g = norig >> 10;
            int rem = norig & 1023;
            int np = ((rem >> 5) << 7) + (((rem >> 3) & 3) << 5) + (g << 3) + (rem & 7);
            int nt = np >> 7;
            uint32_t r = (uint32_t)(np & 127);
            uint32_t kl = (uint32_t)(kbase + kp);
            __half2 hv = __floats2half2_rn(buf[kp][nl], buf[kp + 1][nl]);
            unsigned char* dst = g_Bpack + (((size_t)nt * NT_K + kchunk) << 14);
            *reinterpret_cast<uint32_t*>(dst + swz(r, kl >> 3) + (kl & 7) * 2) =
                *reinterpret_cast<uint32_t*>(&hv);
        }
    }
}

// ---------------------------------------------------------------- main GEMM + epilogue
// grid (64 j-halfblocks, 32 m-blocks), 256 threads = 8 warps (wm 0..3 x wn 0..1),
// CTA tile 128x64, warp tile 32x32 (2 m16 x 4 n8 = gates). 3-stage TMA
// pipeline, full/empty mbarriers. 3 CTAs/SM.
__global__ void __launch_bounds__(256, 3) lstm_main(const float* __restrict__ c_in,
                                                    const float* __restrict__ bias,
                                                    float* __restrict__ out) {
    extern __shared__ __align__(1024) unsigned char smem[];
    const uint32_t sb = smem_u32(smem);
    const int tid  = threadIdx.x;
    const int lane = tid & 31;
    const int warp = tid >> 5;
    const int wm = warp >> 1;       // 0..3 (32 rows)
    const int wn = warp & 1;        // 0..1 (32 B'cols = 4 gates x 8 j)
    const int bx = blockIdx.x;      // 0..63: n' half-block
    const int by = blockIdx.y;      // 0..31: m-block

    const uint32_t FULLB  = sb + SMEM_MAIN;        // full[0..2]
    const uint32_t EMPTYB = sb + SMEM_MAIN + 24;   // empty[0..2]
    if (tid == 0) {
#pragma unroll
        for (int s = 0; s < NSTAGE; ++s) {
            MBARRIER_INIT(FULLB + s * 8, 1);
            MBARRIER_INIT(EMPTYB + s * 8, 8);
        }
    }
    __syncthreads();

    const unsigned char* Ab = g_Apack + ((size_t)by * NT_K << 14);
    const unsigned char* Bb = g_Bpack + (((size_t)(bx >> 1) * NT_K) << 14) + ((size_t)(bx & 1) << 13);

    auto issue = [&](int it) {
        const uint32_t s3 = (uint32_t)(it % NSTAGE);
        const uint32_t bar = FULLB + s3 * 8;
        const uint32_t dst = sb + s3 * STAGE_BYTES;
        MBARRIER_EXPECT_TX(bar, STAGE_BYTES);
        bulk_g2s(dst, Ab + ((size_t)it << 14), A_STAGE, bar);
        bulk_g2s(dst + A_STAGE, Bb + ((size_t)it << 14), B_STAGE, bar);
    };

    if (tid == 0) { issue(0); issue(1); }

    // per-warp ldmatrix bases (csel folded); per-ldsm cost = 1 IADD + 1 XOR
    const uint32_t rlo  = (uint32_t)(lane & 15);
    const uint32_t csel = (uint32_t)(lane >> 4);
    uint32_t pA[2], pB[2];
#pragma unroll
    for (int mt = 0; mt < 2; ++mt) {
        uint32_t rowa = (uint32_t)(wm * 32 + mt * 16) + rlo;
        pA[mt] = sb + rowa * 128u + ((((rowa & 7u) ^ csel) & 7u) << 4);
    }
#pragma unroll
    for (int gp = 0; gp < 2; ++gp) {
        uint32_t rowb = (uint32_t)(wn * 32 + gp * 16) + rlo;
        pB[gp] = sb + A_STAGE + rowb * 128u + ((((rowb & 7u) ^ csel) & 7u) << 4);
    }

    float acc[2][4][4];
#pragma unroll
    for (int i = 0; i < 2; i++)
#pragma unroll
        for (int j = 0; j < 4; j++)
#pragma unroll
            for (int q = 0; q < 4; q++) acc[i][j][q] = 0.0f;

    const int NIT = NT_K;  // 32
    for (int it = 0; it < NIT; ++it) {
        const uint32_t s = (uint32_t)(it % NSTAGE);

        if (tid == 0 && it + 2 < NIT) {
            const int it2 = it + 2;
            const uint32_t s2 = (uint32_t)(it2 % NSTAGE);
            if (it2 >= NSTAGE)
                mbar_wait(EMPTYB + s2 * 8, (uint32_t)(((it2 / NSTAGE) - 1) & 1));
            issue(it2);
        }

        mbar_wait(FULLB + s * 8, (uint32_t)((it / NSTAGE) & 1));

        const uint32_t so = s * STAGE_BYTES;
#pragma unroll
        for (int k16 = 0; k16 < 4; ++k16) {
            const uint32_t kx = (uint32_t)(k16 << 5);
            uint32_t a[2][4];
#pragma unroll
            for (int mt = 0; mt < 2; ++mt) ldsm_x4(a[mt], (pA[mt] + so) ^ kx);
#pragma unroll
            for (int gp = 0; gp < 2; ++gp) {
                uint32_t r4[4];
                ldsm_x4(r4, (pB[gp] + so) ^ kx);
#pragma unroll
                for (int mt = 0; mt < 2; ++mt) {
                    mma16816(acc[mt][2 * gp + 0], a[mt], r4[0], r4[2]);
                    mma16816(acc[mt][2 * gp + 1], a[mt], r4[1], r4[3]);
                }
            }
        }

        if (lane == 0) MBARRIER_ARRIVE(EMPTYB + s * 8);
    }

    // ---- epilogue (fully in-register: nt == gate)
    // warp cols n' in [bx*64 + wn*32, +32): j = 32*(bx>>1) + 8*((bx&1)*2+wn) + jlo
    const int jg = (bx >> 1) * 32 + ((bx & 1) * 2 + wn) * 8 + 2 * (lane & 3);
    float bi[4][2];
#pragma unroll
    for (int g = 0; g < 4; ++g) {
        bi[g][0] = bias[g * 1024 + jg];
        bi[g][1] = bias[g * 1024 + jg + 1];
    }
#pragma unroll
    for (int mt = 0; mt < 2; ++mt) {
#pragma unroll
        for (int hr = 0; hr < 2; ++hr) {
            int m = by * 128 + wm * 32 + mt * 16 + (lane >> 2) + hr * 8;
            const float2 cv = *reinterpret_cast<const float2*>(c_in + (size_t)m * 1024 + jg);
            float hv[2], co[2];
#pragma unroll
            for (int q = 0; q < 2; ++q) {
                float ai = acc[mt][0][hr * 2 + q] + bi[0][q];
                float af = acc[mt][1][hr * 2 + q] + bi[1][q];
                float ao = acc[mt][2][hr * 2 + q] + bi[2][q];
                float ag = acc[mt][3][hr * 2 + q] + bi[3][q];
                float iv = sigm_f(ai);
                float fv = sigm_f(af);
                float ov = sigm_f(ao);
                float gv = tanh_f(ag);
                float cc = (q == 0) ? cv.x : cv.y;
                float c2 = fmaf(iv, gv, fv * cc);
                co[q] = c2;
                hv[q] = ov * tanh_f(c2);
            }
            *reinterpret_cast<float2*>(out + (size_t)m * 1024 + jg) = make_float2(hv[0], hv[1]);
            *reinterpret_cast<float2*>(out + (size_t)BATCH * 1024 + (size_t)m * 1024 + jg) =
                make_float2(co[0], co[1]);
        }
    }
}

// ---------------------------------------------------------------- launch
extern "C" void kernel_launch(void* const* d_in, const int* in_sizes, int n_in,
                              void* d_out, int out_size) {
    (void)in_sizes; (void)n_in; (void)out_size;
    const float* x = (const float*)d_in[0];
    const float* h = (const float*)d_in[1];
    const float* c = (const float*)d_in[2];
    const float* W = (const float*)d_in[3];
    const float* V = (const float*)d_in[4];
    const float* b = (const float*)d_in[5];
    float* out = (float*)d_out;

    cudaFuncSetAttribute(lstm_main, cudaFuncAttributeMaxDynamicSharedMemorySize, SMEM_TOTAL);

    pack_all<<<9216, 256>>>(x, h, W, V);
    lstm_main<<<dim3(64, 32), 256, SMEM_TOTAL>>>(c, b, out);
}